// round 9
// baseline (speedup 1.0000x reference)
#include <cuda_runtime.h>
#include <cuda_fp16.h>
#include <math.h>
#include <stdint.h>

#define TT 1024
#define HH 2048
#define EE 16
#define KTOP 4
#define II 1408
#define ISH 2816

// ---------------- fp32 scratch ----------------
__device__ float g_gu[(size_t)TT * KTOP * 2 * II];
__device__ float g_downbuf[(size_t)TT * KTOP * HH];
__device__ float g_sgu[(size_t)TT * 2 * ISH];
__device__ float g_shdown[(size_t)TT * HH];
__device__ int   g_counts[EE];
__device__ int   g_list[EE * TT];
__device__ float g_tw[TT * KTOP];

// ---------------- fp16 scratch ----------------
__device__ __half g_act_h[(size_t)TT * KTOP * II];
__device__ __half g_shact_h[(size_t)TT * ISH];
__device__ __half g_wg_t[(size_t)EE * II * HH];    // [e][n=II][k=HH]
__device__ __half g_wu_t[(size_t)EE * II * HH];
__device__ __half g_wd_t[(size_t)EE * HH * II];    // [e][n=HH][k=II]
__device__ __half g_swg_t[(size_t)ISH * HH];
__device__ __half g_swu_t[(size_t)ISH * HH];
__device__ __half g_swd_t[(size_t)HH * ISH];

__device__ __forceinline__ float* fbuf_ptr(int sel) {
    switch (sel) {
        case 2: return g_downbuf;
        case 3: return g_sgu;
        case 5: return g_shdown;
        default: return g_gu;
    }
}
__device__ __forceinline__ __half* hbuf_ptr(int sel) {
    switch (sel) {
        case 1: return g_shact_h;
        case 2: return g_wg_t;
        case 3: return g_wu_t;
        case 4: return g_wd_t;
        case 5: return g_swg_t;
        case 6: return g_swu_t;
        case 7: return g_swd_t;
        default: return g_act_h;
    }
}

// ---------------- helpers ----------------
__device__ __forceinline__ uint32_t smem_u32(const void* p) {
    uint32_t a;
    asm("{ .reg .u64 t; cvta.to.shared.u64 t, %1; cvt.u32.u64 %0, t; }" : "=r"(a) : "l"(p));
    return a;
}
__device__ __forceinline__ void ldsm4(uint32_t* r, uint32_t addr) {
    asm volatile("ldmatrix.sync.aligned.m8n8.x4.shared.b16 {%0,%1,%2,%3}, [%4];"
                 : "=r"(r[0]), "=r"(r[1]), "=r"(r[2]), "=r"(r[3]) : "r"(addr));
}
__device__ __forceinline__ void mma16816(float* c, const uint32_t* a, const uint32_t* b) {
    asm volatile(
        "mma.sync.aligned.m16n8k16.row.col.f32.f16.f16.f32 "
        "{%0,%1,%2,%3}, {%4,%5,%6,%7}, {%8,%9}, {%0,%1,%2,%3};"
        : "+f"(c[0]), "+f"(c[1]), "+f"(c[2]), "+f"(c[3])
        : "r"(a[0]), "r"(a[1]), "r"(a[2]), "r"(a[3]), "r"(b[0]), "r"(b[1]));
}
__device__ __forceinline__ uint32_t packh2(float x, float y) {
    __half2 h = __floats2half2_rn(x, y);
    return *(uint32_t*)&h;
}

// ---------------- tile config ----------------
// BK = 32. Row layout: 32 fp16 + 8 pad = 40 elems = 80B stride (conflict-free ldmatrix).
#define RSTRIDE 40
#define TILE_B (128 * RSTRIDE * 2)   // 10240 bytes per operand tile
#define STAGE_B (2 * TILE_B)         // A + B = 20480 bytes per stage

// MODE: 0 = dense, 1 = gather token (A row = code>>2), 2 = gather code
// AF16: 1 = A is fp16 device buffer (a_sel), 0 = A is fp32 external (Aext)
template <int MODE, int AF16>
__global__ void __launch_bounds__(256, 2) gemm_mma(
    const float* __restrict__ Aext, int a_sel, int lda,
    int b1_sel, int b2_sel, int ldbK, int nsplit, long bstride,
    int c_sel, int ldc,
    int Ktot, int Mtot)
{
    __shared__ int codes[128];
    __shared__ __align__(16) char stage[2 * STAGE_B];   // 40 KB static

    float* C = fbuf_ptr(c_sel);

    int e = blockIdx.z;
    int row0 = blockIdx.y * 128;
    int cnt;
    const int* list = nullptr;
    if (MODE != 0) {
        cnt = g_counts[e];
        if (row0 >= cnt) return;
        list = g_list + e * TT;
    } else {
        cnt = Mtot;
        if (row0 >= cnt) return;
    }

    int tid = threadIdx.x;
    int wid = tid >> 5;
    int lane = tid & 31;

    if (tid < 128) {
        int r = row0 + tid;
        if (r >= cnt) r = cnt - 1;
        codes[tid] = (MODE != 0) ? list[r] : r;
    }
    __syncthreads();

    int n0 = blockIdx.x * 128;
    const __half* B;
    {
        int sel = (n0 < nsplit) ? b1_sel : b2_sel;
        int nl = (n0 < nsplit) ? n0 : (n0 - nsplit);
        B = hbuf_ptr(sel) + (size_t)e * bstride + (size_t)nl * ldbK;
    }

    // loader roles: BK = 32
    int arow_idx = tid >> 1, ak0 = (tid & 1) * 16;
    int a_src_row;
    {
        int code = codes[arow_idx];
        a_src_row = (MODE == 1) ? (code >> 2) : code;
    }
    const float* a_basef = nullptr;
    const __half* a_baseh = nullptr;
    if (AF16) a_baseh = hbuf_ptr(a_sel) + (size_t)a_src_row * lda + ak0;
    else      a_basef = Aext + (size_t)a_src_row * lda + ak0;

    int bn = tid & 127, bk0 = (tid >> 7) * 16;
    const __half* b_base = B + (size_t)bn * ldbK + bk0;

    // compute roles
    int wm = (wid >> 2) * 64;
    int wn = (wid & 3) * 32;
    uint32_t sb = smem_u32(stage);
    int lrow = lane & 15, lkh = lane >> 4;
    // B x4 lane mapping: matrix idx = lane>>3; bit0 = k-half, bit1 = n-group
    int b_nrow = ((lane >> 4) & 1) * 8 + (lane & 7);
    int b_khalf = (lane >> 3) & 1;

    float c[4][4][4];
#pragma unroll
    for (int i = 0; i < 4; i++)
#pragma unroll
        for (int j = 0; j < 4; j++)
#pragma unroll
            for (int q = 0; q < 4; q++) c[i][j][q] = 0.f;

    int nt = Ktot >> 5;  // BK = 32

    uint32_t a_pk[8];
    uint4 b_v0, b_v1;

    __half* sA = (__half*)stage;
    __half* sB = (__half*)(stage + TILE_B);

    auto load_tile = [&](int t) {
        if (AF16) {
            const __half* ap = a_baseh + (t << 5);
            uint4 v0 = *(const uint4*)(ap);
            uint4 v1 = *(const uint4*)(ap + 8);
            a_pk[0] = v0.x; a_pk[1] = v0.y; a_pk[2] = v0.z; a_pk[3] = v0.w;
            a_pk[4] = v1.x; a_pk[5] = v1.y; a_pk[6] = v1.z; a_pk[7] = v1.w;
        } else {
            const float* ap = a_basef + (t << 5);
#pragma unroll
            for (int j = 0; j < 4; j++) {
                float4 v = *(const float4*)(ap + j * 4);
                a_pk[j * 2 + 0] = packh2(v.x, v.y);
                a_pk[j * 2 + 1] = packh2(v.z, v.w);
            }
        }
        const __half* bp = b_base + (t << 5);
        b_v0 = *(const uint4*)(bp);
        b_v1 = *(const uint4*)(bp + 8);
    };
    auto store_tile = [&](int s) {
        __half* pA = sA + (size_t)s * (STAGE_B / 2);
        __half* pB = sB + (size_t)s * (STAGE_B / 2);
        int offA = arow_idx * RSTRIDE + ak0;
        *(uint4*)(pA + offA)     = make_uint4(a_pk[0], a_pk[1], a_pk[2], a_pk[3]);
        *(uint4*)(pA + offA + 8) = make_uint4(a_pk[4], a_pk[5], a_pk[6], a_pk[7]);
        int offB = bn * RSTRIDE + bk0;
        *(uint4*)(pB + offB)     = b_v0;
        *(uint4*)(pB + offB + 8) = b_v1;
    };

    // ---- prologue ----
    load_tile(0);
    store_tile(0);
    if (nt > 1) load_tile(1);
    __syncthreads();

    for (int t = 0; t < nt; t++) {
        int s = t & 1;
        uint32_t stA = sb + (uint32_t)s * STAGE_B;
        uint32_t stB = stA + (uint32_t)TILE_B;

#pragma unroll
        for (int kt = 0; kt < 2; kt++) {
            uint32_t bfrag[4][2];
#pragma unroll
            for (int np = 0; np < 2; np++) {   // pairs of n-groups via one ldsm4
                uint32_t r[4];
                uint32_t adr = stB + 2u * (uint32_t)((wn + np * 16 + b_nrow) * RSTRIDE + kt * 16 + b_khalf * 8);
                ldsm4(r, adr);
                bfrag[np * 2 + 0][0] = r[0]; bfrag[np * 2 + 0][1] = r[1];
                bfrag[np * 2 + 1][0] = r[2]; bfrag[np * 2 + 1][1] = r[3];
            }
#pragma unroll
            for (int mi = 0; mi < 4; mi++) {
                uint32_t afrag[4];
                uint32_t adr = stA + 2u * (uint32_t)((wm + mi * 16 + lrow) * RSTRIDE + kt * 16 + lkh * 8);
                ldsm4(afrag, adr);
#pragma unroll
                for (int ni = 0; ni < 4; ni++) {
                    mma16816(c[mi][ni], afrag, bfrag[ni]);
                }
            }
        }

        if (t + 1 < nt) store_tile(1 - s);
        if (t + 2 < nt) load_tile(t + 2);
        __syncthreads();
    }

    // ---- epilogue ----
    int g = lane >> 2, tig = lane & 3;
#pragma unroll
    for (int mi = 0; mi < 4; mi++) {
        int m1 = wm + mi * 16 + g;
        int m2 = m1 + 8;
        bool v1 = (row0 + m1) < cnt;
        bool v2 = (row0 + m2) < cnt;
        int cr1 = codes[m1], cr2 = codes[m2];
        float* p1 = C + (size_t)cr1 * ldc + n0 + wn + tig * 2;
        float* p2 = C + (size_t)cr2 * ldc + n0 + wn + tig * 2;
#pragma unroll
        for (int ni = 0; ni < 4; ni++) {
            if (v1) *(float2*)(p1 + ni * 8) = make_float2(c[mi][ni][0], c[mi][ni][1]);
            if (v2) *(float2*)(p2 + ni * 8) = make_float2(c[mi][ni][2], c[mi][ni][3]);
        }
    }
}

// ---------------- weight transpose+convert: src fp32 [Ks][Ns] -> dst fp16 [Ns][Ks] ----------------
__global__ void transpose_f2h(const float* __restrict__ src, int Ks, int Ns, int dsel) {
    __shared__ float t[32][33];
    int n0 = blockIdx.x * 32, k0 = blockIdx.y * 32;
    int e = blockIdx.z;
    src += (size_t)e * Ks * Ns;
    __half* dst = hbuf_ptr(dsel) + (size_t)e * Ks * Ns;
    int tx = threadIdx.x, ty = threadIdx.y;   // 32 x 8
#pragma unroll
    for (int j = 0; j < 4; j++)
        t[ty + 8 * j][tx] = src[(size_t)(k0 + ty + 8 * j) * Ns + n0 + tx];
    __syncthreads();
#pragma unroll
    for (int j = 0; j < 4; j++)
        dst[(size_t)(n0 + ty + 8 * j) * Ks + k0 + tx] = __float2half(t[tx][ty + 8 * j]);
}

// ---------------- router ----------------
__global__ void zero_counts_kernel() {
    if (threadIdx.x < EE) g_counts[threadIdx.x] = 0;
}

__global__ void router_kernel(const float* __restrict__ x, const float* __restrict__ gw) {
    int t = blockIdx.x * 4 + (threadIdx.x >> 5);
    int lane = threadIdx.x & 31;
    if (t >= TT) return;
    float acc[EE];
#pragma unroll
    for (int e = 0; e < EE; e++) acc[e] = 0.f;
    const float* xr = x + (size_t)t * HH;
    for (int h = lane; h < HH; h += 32) {
        float xv = xr[h];
#pragma unroll
        for (int e = 0; e < EE; e++) acc[e] += xv * gw[e * HH + h];
    }
#pragma unroll
    for (int e = 0; e < EE; e++) {
#pragma unroll
        for (int o = 16; o > 0; o >>= 1) acc[e] += __shfl_xor_sync(0xffffffffu, acc[e], o);
    }
    if (lane == 0) {
        float m = acc[0];
#pragma unroll
        for (int e = 1; e < EE; e++) m = fmaxf(m, acc[e]);
        float sc[EE];
        float sum = 0.f;
#pragma unroll
        for (int e = 0; e < EE; e++) { sc[e] = expf(acc[e] - m); sum += sc[e]; }
        float inv = 1.f / sum;
#pragma unroll
        for (int e = 0; e < EE; e++) sc[e] *= inv;
        int idx[KTOP]; float w[KTOP]; float wsum = 0.f;
#pragma unroll
        for (int k = 0; k < KTOP; k++) {
            int bi = 0; float bv = -1.f;
#pragma unroll
            for (int e = 0; e < EE; e++) if (sc[e] > bv) { bv = sc[e]; bi = e; }
            idx[k] = bi; w[k] = bv; sc[bi] = -2.f; wsum += bv;
        }
        float winv = 1.f / wsum;
        for (int k = 0; k < KTOP; k++) {
            int code = t * KTOP + k;
            g_tw[code] = w[k] * winv;
            int pos = atomicAdd(&g_counts[idx[k]], 1);
            g_list[idx[k] * TT + pos] = code;
        }
    }
}

// ---------------- elementwise ----------------
__global__ void act_routed_kernel() {
    int v = blockIdx.x * blockDim.x + threadIdx.x;
    const int per = II / 4;
    if (v >= TT * KTOP * per) return;
    int code = v / per, c4 = v - code * per;
    const float* row = g_gu + (size_t)code * (2 * II);
    float4 g4 = *(const float4*)(row + c4 * 4);
    float4 u4 = *(const float4*)(row + II + c4 * 4);
    float w = g_tw[code];
    uint2 o;
    o.x = packh2((g4.x / (1.f + __expf(-g4.x))) * u4.x * w,
                 (g4.y / (1.f + __expf(-g4.y))) * u4.y * w);
    o.y = packh2((g4.z / (1.f + __expf(-g4.z))) * u4.z * w,
                 (g4.w / (1.f + __expf(-g4.w))) * u4.w * w);
    *(uint2*)(g_act_h + (size_t)code * II + c4 * 4) = o;
}

__global__ void act_shared_kernel() {
    int v = blockIdx.x * blockDim.x + threadIdx.x;
    const int per = ISH / 4;
    if (v >= TT * per) return;
    int t = v / per, c4 = v - t * per;
    const float* row = g_sgu + (size_t)t * (2 * ISH);
    float4 g4 = *(const float4*)(row + c4 * 4);
    float4 u4 = *(const float4*)(row + ISH + c4 * 4);
    uint2 o;
    o.x = packh2((g4.x / (1.f + __expf(-g4.x))) * u4.x,
                 (g4.y / (1.f + __expf(-g4.y))) * u4.y);
    o.y = packh2((g4.z / (1.f + __expf(-g4.z))) * u4.z,
                 (g4.w / (1.f + __expf(-g4.w))) * u4.w);
    *(uint2*)(g_shact_h + (size_t)t * ISH + c4 * 4) = o;
}

__global__ void combine_kernel(float* __restrict__ out) {
    int v = blockIdx.x * blockDim.x + threadIdx.x;
    const int per = HH / 4;
    if (v >= TT * per) return;
    int t = v / per, h4 = v - t * per;
    float4 acc = *(const float4*)(g_shdown + (size_t)t * HH + h4 * 4);
#pragma unroll
    for (int k = 0; k < KTOP; k++) {
        float4 d = *(const float4*)(g_downbuf + (size_t)(t * KTOP + k) * HH + h4 * 4);
        acc.x += d.x; acc.y += d.y; acc.z += d.z; acc.w += d.w;
    }
    *(float4*)(out + (size_t)t * HH + h4 * 4) = acc;
}

// ---------------- launch ----------------
extern "C" void kernel_launch(void* const* d_in, const int* in_sizes, int n_in,
                              void* d_out, int out_size) {
    const float* x       = (const float*)d_in[0];
    const float* gate_w  = (const float*)d_in[1];
    const float* w_gate  = (const float*)d_in[2];
    const float* w_up    = (const float*)d_in[3];
    const float* w_down  = (const float*)d_in[4];
    const float* sw_gate = (const float*)d_in[5];
    const float* sw_up   = (const float*)d_in[6];
    const float* sw_down = (const float*)d_in[7];
    float* out = (float*)d_out;

    dim3 tb(32, 8);
    // weights -> transposed fp16
    transpose_f2h<<<dim3(II / 32, HH / 32, EE), tb>>>(w_gate, HH, II, 2);
    transpose_f2h<<<dim3(II / 32, HH / 32, EE), tb>>>(w_up, HH, II, 3);
    transpose_f2h<<<dim3(HH / 32, II / 32, EE), tb>>>(w_down, II, HH, 4);
    transpose_f2h<<<dim3(ISH / 32, HH / 32, 1), tb>>>(sw_gate, HH, ISH, 5);
    transpose_f2h<<<dim3(ISH / 32, HH / 32, 1), tb>>>(sw_up, HH, ISH, 6);
    transpose_f2h<<<dim3(HH / 32, ISH / 32, 1), tb>>>(sw_down, ISH, HH, 7);

    zero_counts_kernel<<<1, 32>>>();
    router_kernel<<<TT / 4, 128>>>(x, gate_w);

    // routed gate+up: A = x (fp32), B = wg_t|wu_t, C = g_gu
    gemm_mma<1, 0><<<dim3(2 * II / 128, TT / 128, EE), 256>>>(
        x, 0, HH, 2, 3, HH, II, (long)II * HH, 0, 2 * II, HH, 0);

    // shared gate+up: A = x, B = swg_t|swu_t, C = g_sgu
    gemm_mma<0, 0><<<dim3(2 * ISH / 128, TT / 128, 1), 256>>>(
        x, 0, HH, 5, 6, HH, ISH, 0, 3, 2 * ISH, HH, TT);

    act_routed_kernel<<<(TT * KTOP * (II / 4) + 255) / 256, 256>>>();
    act_shared_kernel<<<(TT * (ISH / 4) + 255) / 256, 256>>>();

    // routed down: A = g_act_h (fp16), B = wd_t, C = g_downbuf
    gemm_mma<2, 1><<<dim3(HH / 128, TT / 128, EE), 256>>>(
        nullptr, 0, II, 4, 4, II, HH, (long)HH * II, 2, HH, II, 0);

    // shared down: A = g_shact_h, B = swd_t, C = g_shdown
    gemm_mma<0, 1><<<dim3(HH / 128, TT / 128, 1), 256>>>(
        nullptr, 1, ISH, 7, 7, ISH, HH, 0, 5, HH, ISH, TT);

    combine_kernel<<<(TT * (HH / 4) + 255) / 256, 256>>>(out);
}

// round 10
// speedup vs baseline: 1.2591x; 1.2591x over previous
#include <cuda_runtime.h>
#include <cuda_fp16.h>
#include <math.h>
#include <stdint.h>

#define TT 1024
#define HH 2048
#define EE 16
#define KTOP 4
#define II 1408
#define ISH 2816

// ---------------- fp32 scratch ----------------
__device__ float g_gu[(size_t)TT * KTOP * 2 * II];
__device__ float g_downbuf[(size_t)TT * KTOP * HH];
__device__ float g_sgu[(size_t)TT * 2 * ISH];
__device__ float g_shdown[(size_t)TT * HH];
__device__ int   g_counts[EE];
__device__ int   g_list[EE * TT];
__device__ float g_tw[TT * KTOP];

// ---------------- fp16 scratch ----------------
__device__ __half g_act_h[(size_t)TT * KTOP * II];
__device__ __half g_shact_h[(size_t)TT * ISH];
__device__ __half g_x_h[(size_t)TT * HH];
__device__ __half g_wg_t[(size_t)EE * II * HH];    // [e][n=II][k=HH]
__device__ __half g_wu_t[(size_t)EE * II * HH];
__device__ __half g_wd_t[(size_t)EE * HH * II];    // [e][n=HH][k=II]
__device__ __half g_swg_t[(size_t)ISH * HH];
__device__ __half g_swu_t[(size_t)ISH * HH];
__device__ __half g_swd_t[(size_t)HH * ISH];

__device__ __forceinline__ float* fbuf_ptr(int sel) {
    switch (sel) {
        case 2: return g_downbuf;
        case 3: return g_sgu;
        case 5: return g_shdown;
        default: return g_gu;
    }
}
__device__ __forceinline__ __half* hbuf_ptr(int sel) {
    switch (sel) {
        case 1: return g_shact_h;
        case 2: return g_wg_t;
        case 3: return g_wu_t;
        case 4: return g_wd_t;
        case 5: return g_swg_t;
        case 6: return g_swu_t;
        case 7: return g_swd_t;
        case 8: return g_x_h;
        default: return g_act_h;
    }
}

// ---------------- helpers ----------------
__device__ __forceinline__ uint32_t smem_u32(const void* p) {
    uint32_t a;
    asm("{ .reg .u64 t; cvta.to.shared.u64 t, %1; cvt.u32.u64 %0, t; }" : "=r"(a) : "l"(p));
    return a;
}
__device__ __forceinline__ void ldsm4(uint32_t* r, uint32_t addr) {
    asm volatile("ldmatrix.sync.aligned.m8n8.x4.shared.b16 {%0,%1,%2,%3}, [%4];"
                 : "=r"(r[0]), "=r"(r[1]), "=r"(r[2]), "=r"(r[3]) : "r"(addr));
}
__device__ __forceinline__ void mma16816(float* c, const uint32_t* a, const uint32_t* b) {
    asm volatile(
        "mma.sync.aligned.m16n8k16.row.col.f32.f16.f16.f32 "
        "{%0,%1,%2,%3}, {%4,%5,%6,%7}, {%8,%9}, {%0,%1,%2,%3};"
        : "+f"(c[0]), "+f"(c[1]), "+f"(c[2]), "+f"(c[3])
        : "r"(a[0]), "r"(a[1]), "r"(a[2]), "r"(a[3]), "r"(b[0]), "r"(b[1]));
}
__device__ __forceinline__ uint32_t packh2(float x, float y) {
    __half2 h = __floats2half2_rn(x, y);
    return *(uint32_t*)&h;
}
__device__ __forceinline__ void cp_async16(uint32_t dst, const void* src) {
    asm volatile("cp.async.cg.shared.global [%0], [%1], 16;" :: "r"(dst), "l"(src) : "memory");
}
__device__ __forceinline__ void cp_commit() {
    asm volatile("cp.async.commit_group;" ::: "memory");
}
__device__ __forceinline__ void cp_wait1() {
    asm volatile("cp.async.wait_group 1;" ::: "memory");
}

// ---------------- tile config ----------------
// BK = 16. Row layout: 16 fp16 + 8 pad = 24 elems = 48B stride.
// 48B stride: 8 consecutive rows -> (3r + c) mod 8 distinct -> conflict-free ldmatrix.
#define RSTRIDE 24
#define TILEB (128 * RSTRIDE * 2)   // 6144 bytes per operand tile
#define STAGEB (2 * TILEB)          // 12288 bytes per stage

// MODE: 0 = dense, 1 = gather token (A row = code>>2), 2 = gather code
template <int MODE>
__global__ void __launch_bounds__(512, 2) gemm_mma(
    int a_sel, int lda,
    int b1_sel, int b2_sel, int ldbK, int nsplit, long bstride,
    int c_sel, int ldc, int Ktot, int Mtot)
{
    __shared__ int codes[128];
    __shared__ __align__(16) char stage[3 * STAGEB];   // 36 KB static

    float* C = fbuf_ptr(c_sel);

    int e = blockIdx.z;
    int row0 = blockIdx.y * 128;
    int cnt;
    const int* list = nullptr;
    if (MODE != 0) {
        cnt = g_counts[e];
        if (row0 >= cnt) return;
        list = g_list + e * TT;
    } else {
        cnt = Mtot;
        if (row0 >= cnt) return;
    }

    int tid = threadIdx.x;
    int wid = tid >> 5;
    int lane = tid & 31;

    if (tid < 128) {
        int r = row0 + tid;
        if (r >= cnt) r = cnt - 1;
        codes[tid] = (MODE != 0) ? list[r] : r;
    }
    __syncthreads();

    int n0 = blockIdx.x * 128;
    const __half* B;
    {
        int sel = (n0 < nsplit) ? b1_sel : b2_sel;
        int nl = (n0 < nsplit) ? n0 : (n0 - nsplit);
        B = hbuf_ptr(sel) + (size_t)e * bstride + (size_t)nl * ldbK;
    }

    // loader role: one 16B cp.async per thread per tile
    uint32_t sb = smem_u32(stage);
    const __half* cp_src;
    uint32_t cp_dst;
    if (tid < 256) {
        int r = tid >> 1, kh = tid & 1;
        int code = codes[r];
        int arow = (MODE == 1) ? (code >> 2) : code;
        cp_src = hbuf_ptr(a_sel) + (size_t)arow * lda + kh * 8;
        cp_dst = (uint32_t)(r * RSTRIDE + kh * 8) * 2u;
    } else {
        int u = tid - 256;
        int n = u >> 1, kh = u & 1;
        cp_src = B + (size_t)n * ldbK + kh * 8;
        cp_dst = (uint32_t)TILEB + (uint32_t)(n * RSTRIDE + kh * 8) * 2u;
    }

    // compute roles: 16 warps, warp tile 32x32
    int wm = (wid >> 2) * 32;
    int wn = (wid & 3) * 32;
    int lrow = lane & 15, lkh = lane >> 4;
    int b_nrow = ((lane >> 4) & 1) * 8 + (lane & 7);
    int b_kh = (lane >> 3) & 1;

    float c[2][4][4];
#pragma unroll
    for (int i = 0; i < 2; i++)
#pragma unroll
        for (int j = 0; j < 4; j++)
#pragma unroll
            for (int q = 0; q < 4; q++) c[i][j][q] = 0.f;

    int nt = Ktot >> 4;  // BK = 16

    auto fetch = [&](int t, int slot) {
        cp_async16(sb + (uint32_t)slot * STAGEB + cp_dst, cp_src + t * 16);
        cp_commit();
    };

    // prologue: tiles 0, 1
    fetch(0, 0);
    fetch(1, 1);

    for (int t = 0; t < nt; t++) {
        cp_wait1();          // group for tile t done
        __syncthreads();     // tile t visible to all; slot (t+2)%3 free
        {
            int tf = t + 2;
            if (tf >= nt) tf = nt - 1;   // redundant fetch keeps group count uniform
            fetch(tf, (t + 2) % 3);
        }

        uint32_t stA = sb + (uint32_t)(t % 3) * STAGEB;
        uint32_t stB = stA + (uint32_t)TILEB;

        uint32_t bfrag[4][2];
#pragma unroll
        for (int np = 0; np < 2; np++) {
            uint32_t r[4];
            ldsm4(r, stB + 2u * (uint32_t)((wn + np * 16 + b_nrow) * RSTRIDE + b_kh * 8));
            bfrag[np * 2 + 0][0] = r[0]; bfrag[np * 2 + 0][1] = r[1];
            bfrag[np * 2 + 1][0] = r[2]; bfrag[np * 2 + 1][1] = r[3];
        }
#pragma unroll
        for (int mi = 0; mi < 2; mi++) {
            uint32_t afrag[4];
            ldsm4(afrag, stA + 2u * (uint32_t)((wm + mi * 16 + lrow) * RSTRIDE + lkh * 8));
#pragma unroll
            for (int ni = 0; ni < 4; ni++)
                mma16816(c[mi][ni], afrag, bfrag[ni]);
        }
    }

    // ---- epilogue ----
    int g = lane >> 2, tig = lane & 3;
#pragma unroll
    for (int mi = 0; mi < 2; mi++) {
        int m1 = wm + mi * 16 + g;
        int m2 = m1 + 8;
        bool v1 = (row0 + m1) < cnt;
        bool v2 = (row0 + m2) < cnt;
        int cr1 = codes[m1], cr2 = codes[m2];
        float* p1 = C + (size_t)cr1 * ldc + n0 + wn + tig * 2;
        float* p2 = C + (size_t)cr2 * ldc + n0 + wn + tig * 2;
#pragma unroll
        for (int ni = 0; ni < 4; ni++) {
            if (v1) *(float2*)(p1 + ni * 8) = make_float2(c[mi][ni][0], c[mi][ni][1]);
            if (v2) *(float2*)(p2 + ni * 8) = make_float2(c[mi][ni][2], c[mi][ni][3]);
        }
    }
}

// ---------------- fast transpose+convert: src fp32 [Ks][Ns] -> dst fp16 [Ns][Ks] ----------------
__global__ void transpose_f2h(const float* __restrict__ src, int Ks, int Ns, int dsel) {
    __shared__ float t[64][65];
    int e = blockIdx.z;
    src += (size_t)e * Ks * Ns;
    __half* dst = hbuf_ptr(dsel) + (size_t)e * Ks * Ns;
    int n0 = blockIdx.x * 64, k0 = blockIdx.y * 64;
    int tid = threadIdx.x;   // 256
    int r = tid >> 4, cq = tid & 15;
#pragma unroll
    for (int j = 0; j < 4; j++) {
        float4 v = *(const float4*)(src + (size_t)(k0 + r + 16 * j) * Ns + n0 + cq * 4);
        t[r + 16 * j][cq * 4 + 0] = v.x;
        t[r + 16 * j][cq * 4 + 1] = v.y;
        t[r + 16 * j][cq * 4 + 2] = v.z;
        t[r + 16 * j][cq * 4 + 3] = v.w;
    }
    __syncthreads();
    int n = tid >> 2, kc = tid & 3;
    uint32_t pk[8];
#pragma unroll
    for (int i = 0; i < 8; i++)
        pk[i] = packh2(t[kc * 16 + 2 * i][n], t[kc * 16 + 2 * i + 1][n]);
    __half* dp = dst + (size_t)(n0 + n) * Ks + k0 + kc * 16;
    *(uint4*)(dp)     = make_uint4(pk[0], pk[1], pk[2], pk[3]);
    *(uint4*)(dp + 8) = make_uint4(pk[4], pk[5], pk[6], pk[7]);
}

// ---------------- x -> fp16 ----------------
__global__ void convert_x(const float* __restrict__ x) {
    int v = blockIdx.x * blockDim.x + threadIdx.x;
    if (v >= TT * HH / 8) return;
    const float4* xp = (const float4*)x + (size_t)v * 2;
    float4 a = xp[0], b = xp[1];
    uint4 o = make_uint4(packh2(a.x, a.y), packh2(a.z, a.w),
                         packh2(b.x, b.y), packh2(b.z, b.w));
    *(uint4*)(g_x_h + (size_t)v * 8) = o;
}

// ---------------- router ----------------
__global__ void zero_counts_kernel() {
    if (threadIdx.x < EE) g_counts[threadIdx.x] = 0;
}

__global__ void router_kernel(const float* __restrict__ x, const float* __restrict__ gw) {
    int t = blockIdx.x * 4 + (threadIdx.x >> 5);
    int lane = threadIdx.x & 31;
    if (t >= TT) return;
    float acc[EE];
#pragma unroll
    for (int e = 0; e < EE; e++) acc[e] = 0.f;
    const float* xr = x + (size_t)t * HH;
    for (int h = lane; h < HH; h += 32) {
        float xv = xr[h];
#pragma unroll
        for (int e = 0; e < EE; e++) acc[e] += xv * gw[e * HH + h];
    }
#pragma unroll
    for (int e = 0; e < EE; e++) {
#pragma unroll
        for (int o = 16; o > 0; o >>= 1) acc[e] += __shfl_xor_sync(0xffffffffu, acc[e], o);
    }
    if (lane == 0) {
        float m = acc[0];
#pragma unroll
        for (int e = 1; e < EE; e++) m = fmaxf(m, acc[e]);
        float sc[EE];
        float sum = 0.f;
#pragma unroll
        for (int e = 0; e < EE; e++) { sc[e] = expf(acc[e] - m); sum += sc[e]; }
        float inv = 1.f / sum;
#pragma unroll
        for (int e = 0; e < EE; e++) sc[e] *= inv;
        int idx[KTOP]; float w[KTOP]; float wsum = 0.f;
#pragma unroll
        for (int k = 0; k < KTOP; k++) {
            int bi = 0; float bv = -1.f;
#pragma unroll
            for (int e = 0; e < EE; e++) if (sc[e] > bv) { bv = sc[e]; bi = e; }
            idx[k] = bi; w[k] = bv; sc[bi] = -2.f; wsum += bv;
        }
        float winv = 1.f / wsum;
        for (int k = 0; k < KTOP; k++) {
            int code = t * KTOP + k;
            g_tw[code] = w[k] * winv;
            int pos = atomicAdd(&g_counts[idx[k]], 1);
            g_list[idx[k] * TT + pos] = code;
        }
    }
}

// ---------------- elementwise ----------------
__global__ void act_routed_kernel() {
    int v = blockIdx.x * blockDim.x + threadIdx.x;
    const int per = II / 4;
    if (v >= TT * KTOP * per) return;
    int code = v / per, c4 = v - code * per;
    const float* row = g_gu + (size_t)code * (2 * II);
    float4 g4 = *(const float4*)(row + c4 * 4);
    float4 u4 = *(const float4*)(row + II + c4 * 4);
    float w = g_tw[code];
    uint2 o;
    o.x = packh2((g4.x / (1.f + __expf(-g4.x))) * u4.x * w,
                 (g4.y / (1.f + __expf(-g4.y))) * u4.y * w);
    o.y = packh2((g4.z / (1.f + __expf(-g4.z))) * u4.z * w,
                 (g4.w / (1.f + __expf(-g4.w))) * u4.w * w);
    *(uint2*)(g_act_h + (size_t)code * II + c4 * 4) = o;
}

__global__ void act_shared_kernel() {
    int v = blockIdx.x * blockDim.x + threadIdx.x;
    const int per = ISH / 4;
    if (v >= TT * per) return;
    int t = v / per, c4 = v - t * per;
    const float* row = g_sgu + (size_t)t * (2 * ISH);
    float4 g4 = *(const float4*)(row + c4 * 4);
    float4 u4 = *(const float4*)(row + ISH + c4 * 4);
    uint2 o;
    o.x = packh2((g4.x / (1.f + __expf(-g4.x))) * u4.x,
                 (g4.y / (1.f + __expf(-g4.y))) * u4.y);
    o.y = packh2((g4.z / (1.f + __expf(-g4.z))) * u4.z,
                 (g4.w / (1.f + __expf(-g4.w))) * u4.w);
    *(uint2*)(g_shact_h + (size_t)t * ISH + c4 * 4) = o;
}

__global__ void combine_kernel(float* __restrict__ out) {
    int v = blockIdx.x * blockDim.x + threadIdx.x;
    const int per = HH / 4;
    if (v >= TT * per) return;
    int t = v / per, h4 = v - t * per;
    float4 acc = *(const float4*)(g_shdown + (size_t)t * HH + h4 * 4);
#pragma unroll
    for (int k = 0; k < KTOP; k++) {
        float4 d = *(const float4*)(g_downbuf + (size_t)(t * KTOP + k) * HH + h4 * 4);
        acc.x += d.x; acc.y += d.y; acc.z += d.z; acc.w += d.w;
    }
    *(float4*)(out + (size_t)t * HH + h4 * 4) = acc;
}

// ---------------- launch ----------------
extern "C" void kernel_launch(void* const* d_in, const int* in_sizes, int n_in,
                              void* d_out, int out_size) {
    const float* x       = (const float*)d_in[0];
    const float* gate_w  = (const float*)d_in[1];
    const float* w_gate  = (const float*)d_in[2];
    const float* w_up    = (const float*)d_in[3];
    const float* w_down  = (const float*)d_in[4];
    const float* sw_gate = (const float*)d_in[5];
    const float* sw_up   = (const float*)d_in[6];
    const float* sw_down = (const float*)d_in[7];
    float* out = (float*)d_out;

    convert_x<<<(TT * HH / 8 + 255) / 256, 256>>>(x);
    transpose_f2h<<<dim3(II / 64, HH / 64, EE), 256>>>(w_gate, HH, II, 2);
    transpose_f2h<<<dim3(II / 64, HH / 64, EE), 256>>>(w_up, HH, II, 3);
    transpose_f2h<<<dim3(HH / 64, II / 64, EE), 256>>>(w_down, II, HH, 4);
    transpose_f2h<<<dim3(ISH / 64, HH / 64, 1), 256>>>(sw_gate, HH, ISH, 5);
    transpose_f2h<<<dim3(ISH / 64, HH / 64, 1), 256>>>(sw_up, HH, ISH, 6);
    transpose_f2h<<<dim3(HH / 64, ISH / 64, 1), 256>>>(sw_down, ISH, HH, 7);

    zero_counts_kernel<<<1, 32>>>();
    router_kernel<<<TT / 4, 128>>>(x, gate_w);

    // routed gate+up: A = x_h (gather token), B = wg_t|wu_t, C = g_gu
    gemm_mma<1><<<dim3(2 * II / 128, TT / 128, EE), 512>>>(
        8, HH, 2, 3, HH, II, (long)II * HH, 0, 2 * II, HH, 0);

    // shared gate+up: A = x_h, B = swg_t|swu_t, C = g_sgu
    gemm_mma<0><<<dim3(2 * ISH / 128, TT / 128, 1), 512>>>(
        8, HH, 5, 6, HH, ISH, 0, 3, 2 * ISH, HH, TT);

    act_routed_kernel<<<(TT * KTOP * (II / 4) + 255) / 256, 256>>>();
    act_shared_kernel<<<(TT * (ISH / 4) + 255) / 256, 256>>>();

    // routed down: A = g_act_h (gather code), B = wd_t, C = g_downbuf
    gemm_mma<2><<<dim3(HH / 128, TT / 128, EE), 512>>>(
        0, II, 4, 4, II, HH, (long)HH * II, 2, HH, II, 0);

    // shared down: A = g_shact_h, B = swd_t, C = g_shdown
    gemm_mma<0><<<dim3(HH / 128, TT / 128, 1), 512>>>(
        1, ISH, 7, 7, ISH, HH, 0, 5, HH, ISH, TT);

    combine_kernel<<<(TT * (HH / 4) + 255) / 256, 256>>>(out);
}

// round 12
// speedup vs baseline: 1.3904x; 1.1042x over previous
#include <cuda_runtime.h>
#include <cuda_fp16.h>
#include <math.h>
#include <stdint.h>

#define TT 1024
#define HH 2048
#define EE 16
#define KTOP 4
#define II 1408
#define ISH 2816

// ---------------- fp32 scratch ----------------
__device__ float g_gu[(size_t)TT * KTOP * 2 * II];
__device__ float g_downbuf[(size_t)TT * KTOP * HH];
__device__ float g_sgu[(size_t)TT * 2 * ISH];
__device__ float g_shdown[(size_t)TT * HH];
__device__ int   g_counts[EE];
__device__ int   g_list[EE * TT];
__device__ float g_tw[TT * KTOP];

// ---------------- fp16 scratch ----------------
__device__ __half g_act_h[(size_t)TT * KTOP * II];
__device__ __half g_shact_h[(size_t)TT * ISH];
__device__ __half g_x_h[(size_t)TT * HH];

__device__ __forceinline__ float* fbuf_ptr(int sel) {
    switch (sel) {
        case 2: return g_downbuf;
        case 3: return g_sgu;
        case 5: return g_shdown;
        default: return g_gu;
    }
}
__device__ __forceinline__ __half* hbuf_ptr(int sel) {
    switch (sel) {
        case 1: return g_shact_h;
        case 2: return g_x_h;
        default: return g_act_h;
    }
}

// ---------------- helpers ----------------
__device__ __forceinline__ uint32_t smem_u32(const void* p) {
    uint32_t a;
    asm("{ .reg .u64 t; cvta.to.shared.u64 t, %1; cvt.u32.u64 %0, t; }" : "=r"(a) : "l"(p));
    return a;
}
__device__ __forceinline__ void ldsm4(uint32_t* r, uint32_t addr) {
    asm volatile("ldmatrix.sync.aligned.m8n8.x4.shared.b16 {%0,%1,%2,%3}, [%4];"
                 : "=r"(r[0]), "=r"(r[1]), "=r"(r[2]), "=r"(r[3]) : "r"(addr));
}
__device__ __forceinline__ void ldsm4t(uint32_t* r, uint32_t addr) {
    asm volatile("ldmatrix.sync.aligned.m8n8.x4.trans.shared.b16 {%0,%1,%2,%3}, [%4];"
                 : "=r"(r[0]), "=r"(r[1]), "=r"(r[2]), "=r"(r[3]) : "r"(addr));
}
__device__ __forceinline__ void mma16816(float* c, const uint32_t* a, const uint32_t* b) {
    asm volatile(
        "mma.sync.aligned.m16n8k16.row.col.f32.f16.f16.f32 "
        "{%0,%1,%2,%3}, {%4,%5,%6,%7}, {%8,%9}, {%0,%1,%2,%3};"
        : "+f"(c[0]), "+f"(c[1]), "+f"(c[2]), "+f"(c[3])
        : "r"(a[0]), "r"(a[1]), "r"(a[2]), "r"(a[3]), "r"(b[0]), "r"(b[1]));
}
__device__ __forceinline__ uint32_t packh2(float x, float y) {
    __half2 h = __floats2half2_rn(x, y);
    return *(uint32_t*)&h;
}
__device__ __forceinline__ void cp_async16(uint32_t dst, const void* src) {
    asm volatile("cp.async.cg.shared.global [%0], [%1], 16;" :: "r"(dst), "l"(src) : "memory");
}
__device__ __forceinline__ void cp_commit() {
    asm volatile("cp.async.commit_group;" ::: "memory");
}
__device__ __forceinline__ void cp_wait0() {
    asm volatile("cp.async.wait_group 0;" ::: "memory");
}

// ---------------- tile config ----------------
// A tile: [m=128][RSTRIDE=40 fp16] (32 k + 8 pad), 80B rows -> (5m + chunk) mod 8 conflict-free.
// B tile: [k=32][136 fp16] (128 n + 8 pad), 272B rows -> (17k + oct) mod 8 conflict-free (trans ldmatrix).
#define RSTRIDE 40
#define A_TILE (128 * RSTRIDE * 2)          // 10240 B
#define BROW 136
#define B_TILE (32 * BROW * 2)              // 8704 B
#define STAGEB (A_TILE + B_TILE)            // 18944 B

// MODE: 0 = dense, 1 = gather token (A row = code>>2), 2 = gather code
template <int MODE>
__global__ void __launch_bounds__(512, 2) gemm_mma(
    int a_sel, int lda,
    const float* __restrict__ B1, const float* __restrict__ B2,
    int ldbN, int nsplit, long bstride,
    int c_sel, int ldc, int Ktot, int Mtot)
{
    __shared__ int codes[128];
    __shared__ __align__(16) char stage[2 * STAGEB];   // 37888 B static

    float* C = fbuf_ptr(c_sel);

    int e = blockIdx.z;
    int row0 = blockIdx.y * 128;
    int cnt;
    const int* list = nullptr;
    if (MODE != 0) {
        cnt = g_counts[e];
        if (row0 >= cnt) return;
        list = g_list + e * TT;
    } else {
        cnt = Mtot;
        if (row0 >= cnt) return;
    }

    int tid = threadIdx.x;
    int wid = tid >> 5;
    int lane = tid & 31;

    if (tid < 128) {
        int r = row0 + tid;
        if (r >= cnt) r = cnt - 1;
        codes[tid] = (MODE != 0) ? list[r] : r;
    }
    __syncthreads();

    int n0 = blockIdx.x * 128;
    const float* B;
    if (n0 < nsplit) B = B1 + (size_t)e * bstride + n0;
    else             B = B2 + (size_t)e * bstride + (n0 - nsplit);

    uint32_t sb = smem_u32(stage);

    // A loader: ar = tid>>2 (row), akh = tid&3 (16B chunk); one cp.async 16B per tile
    int ar = tid >> 2, akh = tid & 3;
    const __half* a_src;
    {
        int code = codes[ar];
        int arow = (MODE == 1) ? (code >> 2) : code;
        a_src = hbuf_ptr(a_sel) + (size_t)arow * lda + akh * 8;
    }
    uint32_t a_dst = (uint32_t)(ar * RSTRIDE + akh * 8) * 2u;

    // B loader: bk = tid>>4 (k row), bth = tid&15 (8-n chunk); 2x LDG.128 fp32 per tile
    int bk = tid >> 4, bth = tid & 15;
    const float* b_src = B + (size_t)bk * ldbN + bth * 8;
    uint32_t b_dst = (uint32_t)A_TILE + (uint32_t)(bk * BROW + bth * 8) * 2u;

    // compute roles: 16 warps, warp tile 32x32
    int wm = (wid >> 2) * 32;
    int wn = (wid & 3) * 32;
    int lrow = lane & 15, lkh = lane >> 4;
    // B trans-ldmatrix lane addressing
    int b_krow = ((lane >> 3) & 1) * 8 + (lane & 7);
    int b_noff = ((lane >> 4) & 1) * 8;

    float c[2][4][4];
#pragma unroll
    for (int i = 0; i < 2; i++)
#pragma unroll
        for (int j = 0; j < 4; j++)
#pragma unroll
            for (int q = 0; q < 4; q++) c[i][j][q] = 0.f;

    int nt = Ktot >> 5;  // BK = 32

    float4 bv0, bv1;

    auto fetchA = [&](int t, int slot) {
        cp_async16(sb + (uint32_t)slot * STAGEB + a_dst, a_src + t * 32);
        cp_commit();
    };
    auto loadB = [&](int t) {
        const float* p = b_src + (size_t)(t * 32) * ldbN;
        bv0 = *(const float4*)(p);
        bv1 = *(const float4*)(p + 4);
    };
    auto storeB = [&](int slot) {
        uint4 o = make_uint4(packh2(bv0.x, bv0.y), packh2(bv0.z, bv0.w),
                             packh2(bv1.x, bv1.y), packh2(bv1.z, bv1.w));
        *(uint4*)(stage + (size_t)slot * STAGEB + b_dst) = o;
    };

    // prologue
    fetchA(0, 0);
    loadB(0);

    for (int t = 0; t < nt; t++) {
        int s = t & 1;
        storeB(s);
        cp_wait0();
        __syncthreads();
        if (t + 1 < nt) {
            fetchA(t + 1, 1 - s);
            loadB(t + 1);
        }

        uint32_t stA = sb + (uint32_t)s * STAGEB;
        uint32_t stB = stA + (uint32_t)A_TILE;

#pragma unroll
        for (int kt = 0; kt < 2; kt++) {
            uint32_t bfrag[4][2];
#pragma unroll
            for (int np = 0; np < 2; np++) {
                uint32_t r[4];
                uint32_t adr = stB + (uint32_t)((kt * 16 + b_krow) * BROW + (wn + np * 16 + b_noff)) * 2u;
                ldsm4t(r, adr);
                bfrag[np * 2 + 0][0] = r[0]; bfrag[np * 2 + 0][1] = r[1];
                bfrag[np * 2 + 1][0] = r[2]; bfrag[np * 2 + 1][1] = r[3];
            }
#pragma unroll
            for (int mi = 0; mi < 2; mi++) {
                uint32_t afrag[4];
                ldsm4(afrag, stA + 2u * (uint32_t)((wm + mi * 16 + lrow) * RSTRIDE + kt * 16 + lkh * 8));
#pragma unroll
                for (int ni = 0; ni < 4; ni++)
                    mma16816(c[mi][ni], afrag, bfrag[ni]);
            }
        }
    }

    // ---- epilogue ----
    int g = lane >> 2, tig = lane & 3;
#pragma unroll
    for (int mi = 0; mi < 2; mi++) {
        int m1 = wm + mi * 16 + g;
        int m2 = m1 + 8;
        bool v1 = (row0 + m1) < cnt;
        bool v2 = (row0 + m2) < cnt;
        int cr1 = codes[m1], cr2 = codes[m2];
        float* p1 = C + (size_t)cr1 * ldc + n0 + wn + tig * 2;
        float* p2 = C + (size_t)cr2 * ldc + n0 + wn + tig * 2;
#pragma unroll
        for (int ni = 0; ni < 4; ni++) {
            if (v1) *(float2*)(p1 + ni * 8) = make_float2(c[mi][ni][0], c[mi][ni][1]);
            if (v2) *(float2*)(p2 + ni * 8) = make_float2(c[mi][ni][2], c[mi][ni][3]);
        }
    }
}

// ---------------- x -> fp16 ----------------
__global__ void convert_x(const float* __restrict__ x) {
    int v = blockIdx.x * blockDim.x + threadIdx.x;
    if (v >= TT * HH / 8) return;
    const float4* xp = (const float4*)x + (size_t)v * 2;
    float4 a = xp[0], b = xp[1];
    uint4 o = make_uint4(packh2(a.x, a.y), packh2(a.z, a.w),
                         packh2(b.x, b.y), packh2(b.z, b.w));
    *(uint4*)(g_x_h + (size_t)v * 8) = o;
}

// ---------------- router ----------------
__global__ void zero_counts_kernel() {
    if (threadIdx.x < EE) g_counts[threadIdx.x] = 0;
}

__global__ void router_kernel(const float* __restrict__ x, const float* __restrict__ gw) {
    int t = blockIdx.x * 4 + (threadIdx.x >> 5);
    int lane = threadIdx.x & 31;
    if (t >= TT) return;
    float acc[EE];
#pragma unroll
    for (int e = 0; e < EE; e++) acc[e] = 0.f;
    const float* xr = x + (size_t)t * HH;
    for (int h = lane; h < HH; h += 32) {
        float xv = xr[h];
#pragma unroll
        for (int e = 0; e < EE; e++) acc[e] += xv * gw[e * HH + h];
    }
#pragma unroll
    for (int e = 0; e < EE; e++) {
#pragma unroll
        for (int o = 16; o > 0; o >>= 1) acc[e] += __shfl_xor_sync(0xffffffffu, acc[e], o);
    }
    if (lane == 0) {
        float m = acc[0];
#pragma unroll
        for (int e = 1; e < EE; e++) m = fmaxf(m, acc[e]);
        float sc[EE];
        float sum = 0.f;
#pragma unroll
        for (int e = 0; e < EE; e++) { sc[e] = expf(acc[e] - m); sum += sc[e]; }
        float inv = 1.f / sum;
#pragma unroll
        for (int e = 0; e < EE; e++) sc[e] *= inv;
        int idx[KTOP]; float w[KTOP]; float wsum = 0.f;
#pragma unroll
        for (int k = 0; k < KTOP; k++) {
            int bi = 0; float bv = -1.f;
#pragma unroll
            for (int e = 0; e < EE; e++) if (sc[e] > bv) { bv = sc[e]; bi = e; }
            idx[k] = bi; w[k] = bv; sc[bi] = -2.f; wsum += bv;
        }
        float winv = 1.f / wsum;
        for (int k = 0; k < KTOP; k++) {
            int code = t * KTOP + k;
            g_tw[code] = w[k] * winv;
            int pos = atomicAdd(&g_counts[idx[k]], 1);
            g_list[idx[k] * TT + pos] = code;
        }
    }
}

// ---------------- elementwise ----------------
__global__ void act_routed_kernel() {
    int v = blockIdx.x * blockDim.x + threadIdx.x;
    const int per = II / 4;
    if (v >= TT * KTOP * per) return;
    int code = v / per, c4 = v - code * per;
    const float* row = g_gu + (size_t)code * (2 * II);
    float4 g4 = *(const float4*)(row + c4 * 4);
    float4 u4 = *(const float4*)(row + II + c4 * 4);
    float w = g_tw[code];
    uint2 o;
    o.x = packh2((g4.x / (1.f + __expf(-g4.x))) * u4.x * w,
                 (g4.y / (1.f + __expf(-g4.y))) * u4.y * w);
    o.y = packh2((g4.z / (1.f + __expf(-g4.z))) * u4.z * w,
                 (g4.w / (1.f + __expf(-g4.w))) * u4.w * w);
    *(uint2*)(g_act_h + (size_t)code * II + c4 * 4) = o;
}

__global__ void act_shared_kernel() {
    int v = blockIdx.x * blockDim.x + threadIdx.x;
    const int per = ISH / 4;
    if (v >= TT * per) return;
    int t = v / per, c4 = v - t * per;
    const float* row = g_sgu + (size_t)t * (2 * ISH);
    float4 g4 = *(const float4*)(row + c4 * 4);
    float4 u4 = *(const float4*)(row + ISH + c4 * 4);
    uint2 o;
    o.x = packh2((g4.x / (1.f + __expf(-g4.x))) * u4.x,
                 (g4.y / (1.f + __expf(-g4.y))) * u4.y);
    o.y = packh2((g4.z / (1.f + __expf(-g4.z))) * u4.z,
                 (g4.w / (1.f + __expf(-g4.w))) * u4.w);
    *(uint2*)(g_shact_h + (size_t)t * ISH + c4 * 4) = o;
}

__global__ void combine_kernel(float* __restrict__ out) {
    int v = blockIdx.x * blockDim.x + threadIdx.x;
    const int per = HH / 4;
    if (v >= TT * per) return;
    int t = v / per, h4 = v - t * per;
    float4 acc = *(const float4*)(g_shdown + (size_t)t * HH + h4 * 4);
#pragma unroll
    for (int k = 0; k < KTOP; k++) {
        float4 d = *(const float4*)(g_downbuf + (size_t)(t * KTOP + k) * HH + h4 * 4);
        acc.x += d.x; acc.y += d.y; acc.z += d.z; acc.w += d.w;
    }
    *(float4*)(out + (size_t)t * HH + h4 * 4) = acc;
}

// ---------------- launch ----------------
extern "C" void kernel_launch(void* const* d_in, const int* in_sizes, int n_in,
                              void* d_out, int out_size) {
    const float* x       = (const float*)d_in[0];
    const float* gate_w  = (const float*)d_in[1];
    const float* w_gate  = (const float*)d_in[2];
    const float* w_up    = (const float*)d_in[3];
    const float* w_down  = (const float*)d_in[4];
    const float* sw_gate = (const float*)d_in[5];
    const float* sw_up   = (const float*)d_in[6];
    const float* sw_down = (const float*)d_in[7];
    float* out = (float*)d_out;

    convert_x<<<(TT * HH / 8 + 255) / 256, 256>>>(x);
    zero_counts_kernel<<<1, 32>>>();
    router_kernel<<<TT / 4, 128>>>(x, gate_w);

    // routed gate+up: A = x_h (gather token), B = w_gate|w_up [k=HH][n=II], C = g_gu
    gemm_mma<1><<<dim3(2 * II / 128, TT / 128, EE), 512>>>(
        2, HH, w_gate, w_up, II, II, (long)HH * II, 0, 2 * II, HH, 0);

    // shared gate+up: A = x_h, B = sw_gate|sw_up [HH][ISH], C = g_sgu
    gemm_mma<0><<<dim3(2 * ISH / 128, TT / 128, 1), 512>>>(
        2, HH, sw_gate, sw_up, ISH, ISH, 0, 3, 2 * ISH, HH, TT);

    act_routed_kernel<<<(TT * KTOP * (II / 4) + 255) / 256, 256>>>();
    act_shared_kernel<<<(TT * (ISH / 4) + 255) / 256, 256>>>();

    // routed down: A = g_act_h (gather code), B = w_down [II][HH], C = g_downbuf
    gemm_mma<2><<<dim3(HH / 128, TT / 128, EE), 512>>>(
        0, II, w_down, w_down, HH, HH, (long)II * HH, 2, HH, II, 0);

    // shared down: A = g_shact_h, B = sw_down [ISH][HH], C = g_shdown
    gemm_mma<0><<<dim3(HH / 128, TT / 128, 1), 512>>>(
        1, ISH, sw_down, sw_down, HH, HH, 0, 5, HH, ISH, TT);

    combine_kernel<<<(TT * (HH / 4) + 255) / 256, 256>>>(out);
}